// round 1
// baseline (speedup 1.0000x reference)
#include <cuda_runtime.h>
#include <math_constants.h>
#include <cstdint>

#define HID 1024
#define NHEADS 16
#define HDIM 64
#define SEQ 2048
#define BT 8192          // B*T
#define TQ 128           // q rows per attention block
#define TK 64            // k rows per tile
#define QPAD 68          // padded Q row stride (words), multiple of 4, !=0 mod 32

// Scratch (static device allocations are allowed; runtime allocs are not)
__device__ float g_qkv[(size_t)BT * 3 * HID];   // [B*T, 3*HID]
__device__ float g_ctx[(size_t)BT * HID];       // [B*T, HID]

// ---------------------------------------------------------------------------
// C[M,N] = A[M,K] @ W[N,K]^T + bias[N]   (torch Linear)
// 128x128 block tile, BK=16, 8x8 per-thread micro-tile, 256 threads.
// M,N,K all multiples of tile sizes for this problem -> no bounds checks.
// ---------------------------------------------------------------------------
__global__ __launch_bounds__(256) void gemm_bias_kernel(
    const float* __restrict__ A, const float* __restrict__ W,
    const float* __restrict__ bias, float* __restrict__ C,
    int M, int N, int K)
{
    const int BM = 128, BN = 128, BK = 16, TM = 8, TN = 8;
    __shared__ float As[BK][BM];
    __shared__ float Bs[BK][BN];

    const int tid = threadIdx.x;
    const size_t brow = (size_t)blockIdx.y * BM;
    const size_t bcol = (size_t)blockIdx.x * BN;
    const int trow = (tid >> 4) * TM;
    const int tcol = (tid & 15) * TN;

    float acc[TM][TN];
#pragma unroll
    for (int i = 0; i < TM; i++)
#pragma unroll
        for (int j = 0; j < TN; j++) acc[i][j] = 0.f;

    const float* Ag = A + brow * K;
    const float* Wg = W + bcol * K;

    for (int kt = 0; kt < K; kt += BK) {
#pragma unroll
        for (int i = 0; i < 2; i++) {
            int idx = i * 256 + tid;
            int r = idx >> 2;
            int c = (idx & 3) * 4;
            float4 a4 = *(const float4*)(Ag + (size_t)r * K + kt + c);
            As[c + 0][r] = a4.x; As[c + 1][r] = a4.y;
            As[c + 2][r] = a4.z; As[c + 3][r] = a4.w;
            float4 b4 = *(const float4*)(Wg + (size_t)r * K + kt + c);
            Bs[c + 0][r] = b4.x; Bs[c + 1][r] = b4.y;
            Bs[c + 2][r] = b4.z; Bs[c + 3][r] = b4.w;
        }
        __syncthreads();
#pragma unroll
        for (int k = 0; k < BK; k++) {
            float am[TM], bn[TN];
            *(float4*)&am[0] = *(const float4*)&As[k][trow];
            *(float4*)&am[4] = *(const float4*)&As[k][trow + 4];
            *(float4*)&bn[0] = *(const float4*)&Bs[k][tcol];
            *(float4*)&bn[4] = *(const float4*)&Bs[k][tcol + 4];
#pragma unroll
            for (int i = 0; i < TM; i++)
#pragma unroll
                for (int j = 0; j < TN; j++)
                    acc[i][j] = fmaf(am[i], bn[j], acc[i][j]);
        }
        __syncthreads();
    }

    float bn[TN];
    *(float4*)&bn[0] = *(const float4*)(bias + bcol + tcol);
    *(float4*)&bn[4] = *(const float4*)(bias + bcol + tcol + 4);
#pragma unroll
    for (int i = 0; i < TM; i++) {
        float* Cp = C + (brow + trow + i) * N + bcol + tcol;
        float4 o0, o1;
        o0.x = acc[i][0] + bn[0]; o0.y = acc[i][1] + bn[1];
        o0.z = acc[i][2] + bn[2]; o0.w = acc[i][3] + bn[3];
        o1.x = acc[i][4] + bn[4]; o1.y = acc[i][5] + bn[5];
        o1.z = acc[i][6] + bn[6]; o1.w = acc[i][7] + bn[7];
        *(float4*)Cp = o0;
        *(float4*)(Cp + 4) = o1;
    }
}

// ---------------------------------------------------------------------------
// Fused causal flash attention, fp32.
// grid = (16 q-tiles, 64 bh), block = 128 threads. Thread t owns query row
// q0+t: S[64] and O[64] accumulators live in registers, K/V tiles in smem
// (reads are warp-broadcast LDS.128 -> conflict-free), Q tile in smem with
// pad-68 rows (lane-strided LDS.128 conflict-free).
// ---------------------------------------------------------------------------
__global__ __launch_bounds__(128) void attn_kernel(
    const float* __restrict__ qkv, float* __restrict__ ctx)
{
    extern __shared__ float sm[];
    float* Qs = sm;                        // 128 x QPAD
    float* Ks = sm + TQ * QPAD;            // 64 x 64
    float* Vs = Ks + TK * 64;              // 64 x 64

    const int tid = threadIdx.x;
    const int qt = blockIdx.x;
    const int bh = blockIdx.y;
    const int b = bh >> 4;
    const int h = bh & 15;
    const int q0 = qt * TQ;
    const int q = q0 + tid;
    const float scale = 0.125f;            // 1/sqrt(64)

    const size_t rs = 3 * HID;             // qkv row stride
    const float* Qg = qkv + ((size_t)b * SEQ + q0) * rs + h * HDIM;
    const float* Kg = qkv + ((size_t)b * SEQ) * rs + HID + h * HDIM;
    const float* Vg = qkv + ((size_t)b * SEQ) * rs + 2 * HID + h * HDIM;

    // cooperative, coalesced Q tile load (pre-scaled)
#pragma unroll
    for (int i = 0; i < 16; i++) {
        int idx = i * 128 + tid;
        int r = idx >> 4;
        int c = (idx & 15) * 4;
        float4 v = *(const float4*)(Qg + (size_t)r * rs + c);
        float* dst = &Qs[r * QPAD + c];
        dst[0] = v.x * scale; dst[1] = v.y * scale;
        dst[2] = v.z * scale; dst[3] = v.w * scale;
    }

    float O[64];
#pragma unroll
    for (int d = 0; d < 64; d++) O[d] = 0.f;
    float m = -CUDART_INF_F;
    float l = 0.f;

    const int kend = q0 + TQ;
    for (int k0 = 0; k0 < kend; k0 += TK) {
        __syncthreads();   // protect Ks/Vs reuse (also orders Q load on iter 0)
#pragma unroll
        for (int i = 0; i < 8; i++) {
            int idx = i * 128 + tid;
            int r = idx >> 4;
            int c = (idx & 15) * 4;
            *(float4*)&Ks[r * 64 + c] = *(const float4*)(Kg + (size_t)(k0 + r) * rs + c);
            *(float4*)&Vs[r * 64 + c] = *(const float4*)(Vg + (size_t)(k0 + r) * rs + c);
        }
        __syncthreads();

        if (q >= k0) {
            float S[64];
#pragma unroll
            for (int j = 0; j < 64; j++) S[j] = 0.f;
#pragma unroll 1
            for (int d4 = 0; d4 < 16; d4++) {
                float4 q4 = *(const float4*)&Qs[tid * QPAD + d4 * 4];
#pragma unroll
                for (int j = 0; j < 64; j++) {
                    float4 k4 = *(const float4*)&Ks[j * 64 + d4 * 4];
                    S[j] = fmaf(q4.x, k4.x,
                           fmaf(q4.y, k4.y,
                           fmaf(q4.z, k4.z,
                           fmaf(q4.w, k4.w, S[j]))));
                }
            }
            // causal mask + running max
            const int jlim = q - k0;       // valid j <= jlim
            float mnew = m;
#pragma unroll
            for (int j = 0; j < 64; j++) {
                if (j > jlim) S[j] = -CUDART_INF_F;
                mnew = fmaxf(mnew, S[j]);
            }
            float corr = __expf(m - mnew);
            m = mnew;
            float lsum = 0.f;
#pragma unroll
            for (int j = 0; j < 64; j++) {
                float p = __expf(S[j] - mnew);
                S[j] = p;
                lsum += p;
            }
            l = l * corr + lsum;
#pragma unroll
            for (int d = 0; d < 64; d++) O[d] *= corr;
            // O += P @ V  (V rows broadcast across the warp)
#pragma unroll
            for (int j = 0; j < 64; j++) {
                float p = S[j];
#pragma unroll
                for (int d4 = 0; d4 < 16; d4++) {
                    float4 v4 = *(const float4*)&Vs[j * 64 + d4 * 4];
                    O[d4 * 4 + 0] = fmaf(p, v4.x, O[d4 * 4 + 0]);
                    O[d4 * 4 + 1] = fmaf(p, v4.y, O[d4 * 4 + 1]);
                    O[d4 * 4 + 2] = fmaf(p, v4.z, O[d4 * 4 + 2]);
                    O[d4 * 4 + 3] = fmaf(p, v4.w, O[d4 * 4 + 3]);
                }
            }
        }
    }

    const float inv = 1.f / l;
    float* out = ctx + ((size_t)b * SEQ + q) * HID + h * HDIM;
#pragma unroll
    for (int d4 = 0; d4 < 16; d4++) {
        float4 o;
        o.x = O[d4 * 4 + 0] * inv;
        o.y = O[d4 * 4 + 1] * inv;
        o.z = O[d4 * 4 + 2] * inv;
        o.w = O[d4 * 4 + 3] * inv;
        *(float4*)(out + d4 * 4) = o;
    }
}

// ---------------------------------------------------------------------------
extern "C" void kernel_launch(void* const* d_in, const int* in_sizes, int n_in,
                              void* d_out, int out_size)
{
    (void)in_sizes; (void)n_in; (void)out_size;
    const float* x     = (const float*)d_in[0];
    // d_in[1] is the causal mask (tril) -- structure is known, not re-read
    const float* W_qkv = (const float*)d_in[2];
    const float* b_qkv = (const float*)d_in[3];
    const float* W_out = (const float*)d_in[4];
    const float* b_out = (const float*)d_in[5];
    float* out = (float*)d_out;

    float* qkv = nullptr;
    float* ctx = nullptr;
    cudaGetSymbolAddress((void**)&qkv, g_qkv);
    cudaGetSymbolAddress((void**)&ctx, g_ctx);

    const size_t attn_smem = (size_t)(TQ * QPAD + TK * 64 * 2) * sizeof(float);
    cudaFuncSetAttribute(attn_kernel,
                         cudaFuncAttributeMaxDynamicSharedMemorySize,
                         (int)attn_smem);

    // 1) QKV projection: [8192,1024] @ [3072,1024]^T + b -> g_qkv
    dim3 g1(3 * HID / 128, BT / 128);
    gemm_bias_kernel<<<g1, 256>>>(x, W_qkv, b_qkv, qkv, BT, 3 * HID, HID);

    // 2) fused causal attention -> g_ctx ([B,T,HID] head-concat layout)
    dim3 ga(SEQ / TQ, 4 * NHEADS);
    attn_kernel<<<ga, 128, attn_smem>>>(qkv, ctx);

    // 3) output projection: [8192,1024] @ [1024,1024]^T + b -> d_out
    dim3 g2(HID / 128, BT / 128);
    gemm_bias_kernel<<<g2, 256>>>(ctx, W_out, b_out, out, BT, HID, HID);
}

// round 3
// speedup vs baseline: 1.2620x; 1.2620x over previous
#include <cuda_runtime.h>
#include <cuda_bf16.h>
#include <math_constants.h>
#include <cstdint>

#define HID 1024
#define NHEADS 16
#define HDIM 64
#define SEQ 2048
#define BT 8192
#define TQ 128
#define TK 64
#define QPAD 68
#define K2 3072            // split-GEMM K' = 3*HID
#define GSTEPS (K2 / 64)   // 48 k-steps of 64 bf16

// ---------------------------------------------------------------------------
// Scratch (__device__ globals: runtime allocation is forbidden)
// ---------------------------------------------------------------------------
__device__ float         g_qkv[(size_t)BT * 3 * HID];     // fp32 [BT, 3H]
__device__ __nv_bfloat16 g_a2x[(size_t)BT * K2];          // [Ah|Al|Ah] of x
__device__ __nv_bfloat16 g_w2qkv[(size_t)3 * HID * K2];   // [Wh|Wh|Wl] of W_qkv
__device__ __nv_bfloat16 g_a2ctx[(size_t)BT * K2];        // [Ah|Al|Ah] of ctx
__device__ __nv_bfloat16 g_w2out[(size_t)HID * K2];       // [Wh|Wh|Wl] of W_out

// ---------------------------------------------------------------------------
// helpers
// ---------------------------------------------------------------------------
__device__ __forceinline__ uint32_t smem_to_u32(const void* p) {
    uint32_t a;
    asm("{ .reg .u64 t; cvta.to.shared.u64 t, %1; cvt.u32.u64 %0, t; }"
        : "=r"(a) : "l"(p));
    return a;
}
#define SW128(b) ((b) ^ (((b) >> 3) & 0x70u))

__device__ __forceinline__ void ldsm_x4(uint32_t* r, uint32_t addr) {
    asm volatile("ldmatrix.sync.aligned.m8n8.x4.shared.b16 {%0,%1,%2,%3}, [%4];"
        : "=r"(r[0]), "=r"(r[1]), "=r"(r[2]), "=r"(r[3]) : "r"(addr));
}
__device__ __forceinline__ void ldsm_x2(uint32_t* r, uint32_t addr) {
    asm volatile("ldmatrix.sync.aligned.m8n8.x2.shared.b16 {%0,%1}, [%2];"
        : "=r"(r[0]), "=r"(r[1]) : "r"(addr));
}
__device__ __forceinline__ void mma16816(float* d, const uint32_t* a, const uint32_t* b) {
    asm volatile("mma.sync.aligned.m16n8k16.row.col.f32.bf16.bf16.f32 "
        "{%0,%1,%2,%3}, {%4,%5,%6,%7}, {%8,%9}, {%0,%1,%2,%3};"
        : "+f"(d[0]), "+f"(d[1]), "+f"(d[2]), "+f"(d[3])
        : "r"(a[0]), "r"(a[1]), "r"(a[2]), "r"(a[3]), "r"(b[0]), "r"(b[1]));
}

__device__ __forceinline__ uint32_t pack2bf(float a, float b) {
    __nv_bfloat162 t = __floats2bfloat162_rn(a, b);
    return *reinterpret_cast<uint32_t*>(&t);
}

// ---------------------------------------------------------------------------
// Split convert: src fp32 [rows, K] -> dst bf16 [rows, 3K]
//   block 0 = hi; block lo_blk = lo; block hi2_blk = hi (duplicate)
//   A-side: lo_blk=1, hi2_blk=2.  W-side: lo_blk=2, hi2_blk=1.
// ---------------------------------------------------------------------------
__global__ __launch_bounds__(256) void split_kernel(
    const float* __restrict__ src, __nv_bfloat16* __restrict__ dst,
    int K, size_t total4, int lo_blk, int hi2_blk)
{
    size_t idx = (size_t)blockIdx.x * blockDim.x + threadIdx.x;
    if (idx >= total4) return;
    int kq = K >> 2;
    size_t r = idx / kq;
    int c = (int)(idx % kq) << 2;
    float4 v = *(const float4*)(src + r * K + c);

    __nv_bfloat16 h0 = __float2bfloat16(v.x), h1 = __float2bfloat16(v.y);
    __nv_bfloat16 h2 = __float2bfloat16(v.z), h3 = __float2bfloat16(v.w);
    float l0 = v.x - __bfloat162float(h0), l1 = v.y - __bfloat162float(h1);
    float l2 = v.z - __bfloat162float(h2), l3 = v.w - __bfloat162float(h3);

    uint2 hi = make_uint2(pack2bf(__bfloat162float(h0), __bfloat162float(h1)),
                          pack2bf(__bfloat162float(h2), __bfloat162float(h3)));
    uint2 lo = make_uint2(pack2bf(l0, l1), pack2bf(l2, l3));

    __nv_bfloat16* drow = dst + r * (size_t)(3 * K);
    *(uint2*)(drow + c) = hi;
    *(uint2*)(drow + (size_t)lo_blk * K + c) = lo;
    *(uint2*)(drow + (size_t)hi2_blk * K + c) = hi;
}

// ---------------------------------------------------------------------------
// mma.sync bf16 GEMM: C[M,N] = A2[M,K2] @ W2[N,K2]^T + bias
// CTA tile 128x128, BK=64, 256 threads (8 warps, 2x4), warp tile 64x32.
// SW128-swizzled smem (128B rows), double buffered.
// ---------------------------------------------------------------------------
__global__ __launch_bounds__(256) void gemm_mma_kernel(
    const __nv_bfloat16* __restrict__ A2, const __nv_bfloat16* __restrict__ W2,
    const float* __restrict__ bias, float* __restrict__ C, int N)
{
    extern __shared__ char dsm[];
    const uint32_t dyn = smem_to_u32(dsm);
    const uint32_t base = (dyn + 1023u) & ~1023u;
    char* dbase = dsm + (base - dyn);
    // layout: buf0: A[16K] B[16K]; buf1: A[16K] B[16K]

    const int tid = threadIdx.x;
    const int lane = tid & 31;
    const int wid = tid >> 5;
    const int wm = wid >> 2;          // 0..1
    const int wn = wid & 3;           // 0..3
    const size_t m0 = (size_t)blockIdx.y * 128;
    const size_t n0 = (size_t)blockIdx.x * 128;

    // global load mapping: thread -> (row = tid>>1, 32-bf16 half = tid&1)
    const int arow = tid >> 1;
    const int ahalf = tid & 1;
    const __nv_bfloat16* gA = A2 + (m0 + arow) * K2 + ahalf * 32;
    const __nv_bfloat16* gB = W2 + (n0 + arow) * K2 + ahalf * 32;
    const uint32_t sts_off = (uint32_t)arow * 128u + (uint32_t)ahalf * 64u;

    float acc[4][4][4];
#pragma unroll
    for (int i = 0; i < 4; i++)
#pragma unroll
        for (int j = 0; j < 4; j++)
#pragma unroll
            for (int r = 0; r < 4; r++) acc[i][j][r] = 0.f;

    // preload buffer 0
    {
        char* smA = dbase;
        char* smB = dbase + 16384;
#pragma unroll
        for (int j = 0; j < 4; j++) {
            uint32_t sw = SW128(sts_off + j * 16u);
            *(float4*)(smA + sw) = *(const float4*)(gA + j * 8);
            *(float4*)(smB + sw) = *(const float4*)(gB + j * 8);
        }
    }
    __syncthreads();

    for (int s = 0; s < GSTEPS; s++) {
        // prefetch next step into registers
        uint4 ra[4], rb[4];
        if (s + 1 < GSTEPS) {
            const int k0 = (s + 1) * 64;
#pragma unroll
            for (int j = 0; j < 4; j++) {
                ra[j] = *(const uint4*)(gA + k0 + j * 8);
                rb[j] = *(const uint4*)(gB + k0 + j * 8);
            }
        }

        const uint32_t abase = base + (uint32_t)(s & 1) * 32768u;
        const uint32_t bbase = abase + 16384u;

#pragma unroll
        for (int kat = 0; kat < 4; kat++) {
            uint32_t af[4][4], bf[4][2];
#pragma unroll
            for (int i = 0; i < 4; i++) {
                uint32_t row = (uint32_t)(wm * 64 + i * 16 + (lane & 15));
                uint32_t byte = row * 128u + (uint32_t)kat * 32u + ((lane >> 4) << 4);
                ldsm_x4(af[i], abase + SW128(byte));
            }
#pragma unroll
            for (int j = 0; j < 4; j++) {
                uint32_t row = (uint32_t)(wn * 32 + j * 8 + (lane & 7));
                uint32_t byte = row * 128u + (uint32_t)kat * 32u + (((lane >> 3) & 1) << 4);
                ldsm_x2(bf[j], bbase + SW128(byte));
            }
#pragma unroll
            for (int i = 0; i < 4; i++)
#pragma unroll
                for (int j = 0; j < 4; j++)
                    mma16816(acc[i][j], af[i], bf[j]);
        }

        if (s + 1 < GSTEPS) {
            char* smA = dbase + ((s + 1) & 1) * 32768;
            char* smB = smA + 16384;
#pragma unroll
            for (int j = 0; j < 4; j++) {
                uint32_t sw = SW128(sts_off + j * 16u);
                *(float4*)(smA + sw) = *(float4*)&ra[j];
                *(float4*)(smB + sw) = *(float4*)&rb[j];
            }
        }
        __syncthreads();
    }

    // epilogue
    const int g = lane >> 2;
    const int tig = lane & 3;
#pragma unroll
    for (int i = 0; i < 4; i++) {
        const size_t r0 = m0 + wm * 64 + i * 16 + g;
#pragma unroll
        for (int j = 0; j < 4; j++) {
            const int col = (int)n0 + wn * 32 + j * 8 + tig * 2;
            float2 bb = *(const float2*)(bias + col);
            float2 o0 = make_float2(acc[i][j][0] + bb.x, acc[i][j][1] + bb.y);
            float2 o1 = make_float2(acc[i][j][2] + bb.x, acc[i][j][3] + bb.y);
            *(float2*)(C + r0 * N + col) = o0;
            *(float2*)(C + (r0 + 8) * N + col) = o1;
        }
    }
}

// ---------------------------------------------------------------------------
// Fused causal flash attention (fp32 FFMA), writes split-bf16 ctx directly.
// ---------------------------------------------------------------------------
__global__ __launch_bounds__(128) void attn_kernel(
    const float* __restrict__ qkv, __nv_bfloat16* __restrict__ a2ctx)
{
    extern __shared__ float sm[];
    float* Qs = sm;
    float* Ks = sm + TQ * QPAD;
    float* Vs = Ks + TK * 64;

    const int tid = threadIdx.x;
    const int qt = blockIdx.x;
    const int bh = blockIdx.y;
    const int b = bh >> 4;
    const int hd = bh & 15;
    const int q0 = qt * TQ;
    const int q = q0 + tid;
    const float scale = 0.125f;

    const size_t rs = 3 * HID;
    const float* Qg = qkv + ((size_t)b * SEQ + q0) * rs + hd * HDIM;
    const float* Kg = qkv + ((size_t)b * SEQ) * rs + HID + hd * HDIM;
    const float* Vg = qkv + ((size_t)b * SEQ) * rs + 2 * HID + hd * HDIM;

#pragma unroll
    for (int i = 0; i < 16; i++) {
        int idx = i * 128 + tid;
        int r = idx >> 4;
        int c = (idx & 15) * 4;
        float4 v = *(const float4*)(Qg + (size_t)r * rs + c);
        float* dst = &Qs[r * QPAD + c];
        dst[0] = v.x * scale; dst[1] = v.y * scale;
        dst[2] = v.z * scale; dst[3] = v.w * scale;
    }

    float O[64];
#pragma unroll
    for (int d = 0; d < 64; d++) O[d] = 0.f;
    float m = -CUDART_INF_F;
    float l = 0.f;

    const int kend = q0 + TQ;
    for (int k0 = 0; k0 < kend; k0 += TK) {
        __syncthreads();
#pragma unroll
        for (int i = 0; i < 8; i++) {
            int idx = i * 128 + tid;
            int r = idx >> 4;
            int c = (idx & 15) * 4;
            *(float4*)&Ks[r * 64 + c] = *(const float4*)(Kg + (size_t)(k0 + r) * rs + c);
            *(float4*)&Vs[r * 64 + c] = *(const float4*)(Vg + (size_t)(k0 + r) * rs + c);
        }
        __syncthreads();

        if (q >= k0) {
            float S[64];
#pragma unroll
            for (int j = 0; j < 64; j++) S[j] = 0.f;
#pragma unroll 1
            for (int d4 = 0; d4 < 16; d4++) {
                float4 q4 = *(const float4*)&Qs[tid * QPAD + d4 * 4];
#pragma unroll
                for (int j = 0; j < 64; j++) {
                    float4 k4 = *(const float4*)&Ks[j * 64 + d4 * 4];
                    S[j] = fmaf(q4.x, k4.x, fmaf(q4.y, k4.y,
                           fmaf(q4.z, k4.z, fmaf(q4.w, k4.w, S[j]))));
                }
            }
            const int jlim = q - k0;
            float mnew = m;
#pragma unroll
            for (int j = 0; j < 64; j++) {
                if (j > jlim) S[j] = -CUDART_INF_F;
                mnew = fmaxf(mnew, S[j]);
            }
            float corr = __expf(m - mnew);
            m = mnew;
            float lsum = 0.f;
#pragma unroll
            for (int j = 0; j < 64; j++) {
                float p = __expf(S[j] - mnew);
                S[j] = p;
                lsum += p;
            }
            l = l * corr + lsum;
#pragma unroll
            for (int d = 0; d < 64; d++) O[d] *= corr;
#pragma unroll
            for (int j = 0; j < 64; j++) {
                float p = S[j];
#pragma unroll
                for (int d4 = 0; d4 < 16; d4++) {
                    float4 v4 = *(const float4*)&Vs[j * 64 + d4 * 4];
                    O[d4 * 4 + 0] = fmaf(p, v4.x, O[d4 * 4 + 0]);
                    O[d4 * 4 + 1] = fmaf(p, v4.y, O[d4 * 4 + 1]);
                    O[d4 * 4 + 2] = fmaf(p, v4.z, O[d4 * 4 + 2]);
                    O[d4 * 4 + 3] = fmaf(p, v4.w, O[d4 * 4 + 3]);
                }
            }
        }
    }

    // epilogue: split ctx into [hi | lo | hi] bf16 row of width 3*HID
    const float inv = 1.f / l;
    __nv_bfloat16* rowp = a2ctx + ((size_t)b * SEQ + q) * K2 + hd * HDIM;
#pragma unroll
    for (int d4 = 0; d4 < 16; d4++) {
        float o0 = O[d4 * 4 + 0] * inv, o1 = O[d4 * 4 + 1] * inv;
        float o2 = O[d4 * 4 + 2] * inv, o3 = O[d4 * 4 + 3] * inv;
        __nv_bfloat16 h0 = __float2bfloat16(o0), h1 = __float2bfloat16(o1);
        __nv_bfloat16 h2 = __float2bfloat16(o2), h3 = __float2bfloat16(o3);
        uint2 hi = make_uint2(pack2bf(__bfloat162float(h0), __bfloat162float(h1)),
                              pack2bf(__bfloat162float(h2), __bfloat162float(h3)));
        uint2 lo = make_uint2(pack2bf(o0 - __bfloat162float(h0), o1 - __bfloat162float(h1)),
                              pack2bf(o2 - __bfloat162float(h2), o3 - __bfloat162float(h3)));
        *(uint2*)(rowp + d4 * 4) = hi;
        *(uint2*)(rowp + HID + d4 * 4) = lo;
        *(uint2*)(rowp + 2 * HID + d4 * 4) = hi;
    }
}

// ---------------------------------------------------------------------------
extern "C" void kernel_launch(void* const* d_in, const int* in_sizes, int n_in,
                              void* d_out, int out_size)
{
    (void)in_sizes; (void)n_in; (void)out_size;
    const float* x     = (const float*)d_in[0];
    const float* W_qkv = (const float*)d_in[2];
    const float* b_qkv = (const float*)d_in[3];
    const float* W_out = (const float*)d_in[4];
    const float* b_out = (const float*)d_in[5];
    float* out = (float*)d_out;

    float* qkv = nullptr;
    __nv_bfloat16 *a2x = nullptr, *w2qkv = nullptr, *a2ctx = nullptr, *w2out = nullptr;
    cudaGetSymbolAddress((void**)&qkv, g_qkv);
    cudaGetSymbolAddress((void**)&a2x, g_a2x);
    cudaGetSymbolAddress((void**)&w2qkv, g_w2qkv);
    cudaGetSymbolAddress((void**)&a2ctx, g_a2ctx);
    cudaGetSymbolAddress((void**)&w2out, g_w2out);

    const int gemm_smem = 64 * 1024 + 1024;
    cudaFuncSetAttribute(gemm_mma_kernel, cudaFuncAttributeMaxDynamicSharedMemorySize, gemm_smem);
    const size_t attn_smem = (size_t)(TQ * QPAD + TK * 64 * 2) * sizeof(float);
    cudaFuncSetAttribute(attn_kernel, cudaFuncAttributeMaxDynamicSharedMemorySize, (int)attn_smem);

    // 0) split-precision conversions
    split_kernel<<<(BT * HID / 4 + 255) / 256, 256>>>(x, a2x, HID, (size_t)BT * HID / 4, 1, 2);
    split_kernel<<<(3 * HID * HID / 4 + 255) / 256, 256>>>(W_qkv, w2qkv, HID, (size_t)3 * HID * HID / 4, 2, 1);
    split_kernel<<<(HID * HID / 4 + 255) / 256, 256>>>(W_out, w2out, HID, (size_t)HID * HID / 4, 2, 1);

    // 1) QKV projection (HMMA): [8192,3072] x [3072,3072]^T
    gemm_mma_kernel<<<dim3(3 * HID / 128, BT / 128), 256, gemm_smem>>>(a2x, w2qkv, b_qkv, qkv, 3 * HID);

    // 2) fused causal attention -> split-bf16 ctx
    attn_kernel<<<dim3(SEQ / TQ, 4 * NHEADS), 128, attn_smem>>>(qkv, a2ctx);

    // 3) output projection (HMMA): [8192,3072] x [1024,3072]^T
    gemm_mma_kernel<<<dim3(HID / 128, BT / 128), 256, gemm_smem>>>(a2ctx, w2out, b_out, out, HID);
}

// round 4
// speedup vs baseline: 1.2622x; 1.0002x over previous
#include <cuda_runtime.h>
#include <cuda_bf16.h>
#include <math_constants.h>
#include <cstdint>

#define HID 1024
#define NHEADS 16
#define HDIM 64
#define SEQ 2048
#define BT 8192
#define TQ 128
#define TK 64
#define QPAD 68
#define K2 3072            // split-GEMM K' = 3*HID
#define GSTEPS (K2 / 64)   // 48 k-steps of 64 bf16

// ---------------------------------------------------------------------------
// Scratch (__device__ globals: runtime allocation is forbidden)
// ---------------------------------------------------------------------------
__device__ float         g_qkv[(size_t)BT * 3 * HID];     // fp32 [BT, 3H]
__device__ __nv_bfloat16 g_a2x[(size_t)BT * K2];          // [Ah|Al|Ah] of x
__device__ __nv_bfloat16 g_w2qkv[(size_t)3 * HID * K2];   // [Wh|Wh|Wl] of W_qkv
__device__ __nv_bfloat16 g_a2ctx[(size_t)BT * K2];        // [Ah|Al|Ah] of ctx
__device__ __nv_bfloat16 g_w2out[(size_t)HID * K2];       // [Wh|Wh|Wl] of W_out

// ---------------------------------------------------------------------------
// helpers
// ---------------------------------------------------------------------------
__device__ __forceinline__ uint32_t smem_to_u32(const void* p) {
    uint32_t a;
    asm("{ .reg .u64 t; cvta.to.shared.u64 t, %1; cvt.u32.u64 %0, t; }"
        : "=r"(a) : "l"(p));
    return a;
}
#define SW128(b) ((b) ^ (((b) >> 3) & 0x70u))

__device__ __forceinline__ void ldsm_x4(uint32_t* r, uint32_t addr) {
    asm volatile("ldmatrix.sync.aligned.m8n8.x4.shared.b16 {%0,%1,%2,%3}, [%4];"
        : "=r"(r[0]), "=r"(r[1]), "=r"(r[2]), "=r"(r[3]) : "r"(addr));
}
__device__ __forceinline__ void ldsm_x2(uint32_t* r, uint32_t addr) {
    asm volatile("ldmatrix.sync.aligned.m8n8.x2.shared.b16 {%0,%1}, [%2];"
        : "=r"(r[0]), "=r"(r[1]) : "r"(addr));
}
__device__ __forceinline__ void mma16816(float* d, const uint32_t* a, const uint32_t* b) {
    asm volatile("mma.sync.aligned.m16n8k16.row.col.f32.bf16.bf16.f32 "
        "{%0,%1,%2,%3}, {%4,%5,%6,%7}, {%8,%9}, {%0,%1,%2,%3};"
        : "+f"(d[0]), "+f"(d[1]), "+f"(d[2]), "+f"(d[3])
        : "r"(a[0]), "r"(a[1]), "r"(a[2]), "r"(a[3]), "r"(b[0]), "r"(b[1]));
}

__device__ __forceinline__ uint32_t pack2bf(float a, float b) {
    __nv_bfloat162 t = __floats2bfloat162_rn(a, b);
    return *reinterpret_cast<uint32_t*>(&t);
}

// ---------------------------------------------------------------------------
// Split convert: src fp32 [rows, K] -> dst bf16 [rows, 3K]
//   block 0 = hi; block lo_blk = lo; block hi2_blk = hi (duplicate)
//   A-side: lo_blk=1, hi2_blk=2.  W-side: lo_blk=2, hi2_blk=1.
// ---------------------------------------------------------------------------
__global__ __launch_bounds__(256) void split_kernel(
    const float* __restrict__ src, __nv_bfloat16* __restrict__ dst,
    int K, size_t total4, int lo_blk, int hi2_blk)
{
    size_t idx = (size_t)blockIdx.x * blockDim.x + threadIdx.x;
    if (idx >= total4) return;
    int kq = K >> 2;
    size_t r = idx / kq;
    int c = (int)(idx % kq) << 2;
    float4 v = *(const float4*)(src + r * K + c);

    __nv_bfloat16 h0 = __float2bfloat16(v.x), h1 = __float2bfloat16(v.y);
    __nv_bfloat16 h2 = __float2bfloat16(v.z), h3 = __float2bfloat16(v.w);
    float l0 = v.x - __bfloat162float(h0), l1 = v.y - __bfloat162float(h1);
    float l2 = v.z - __bfloat162float(h2), l3 = v.w - __bfloat162float(h3);

    uint2 hi = make_uint2(pack2bf(__bfloat162float(h0), __bfloat162float(h1)),
                          pack2bf(__bfloat162float(h2), __bfloat162float(h3)));
    uint2 lo = make_uint2(pack2bf(l0, l1), pack2bf(l2, l3));

    __nv_bfloat16* drow = dst + r * (size_t)(3 * K);
    *(uint2*)(drow + c) = hi;
    *(uint2*)(drow + (size_t)lo_blk * K + c) = lo;
    *(uint2*)(drow + (size_t)hi2_blk * K + c) = hi;
}

// ---------------------------------------------------------------------------
// mma.sync bf16 GEMM: C[M,N] = A2[M,K2] @ W2[N,K2]^T + bias
// CTA tile 128x128, BK=64, 256 threads (8 warps, 2x4), warp tile 64x32.
// SW128-swizzled smem (128B rows), double buffered.
// ---------------------------------------------------------------------------
__global__ __launch_bounds__(256) void gemm_mma_kernel(
    const __nv_bfloat16* __restrict__ A2, const __nv_bfloat16* __restrict__ W2,
    const float* __restrict__ bias, float* __restrict__ C, int N)
{
    extern __shared__ char dsm[];
    const uint32_t dyn = smem_to_u32(dsm);
    const uint32_t base = (dyn + 1023u) & ~1023u;
    char* dbase = dsm + (base - dyn);
    // layout: buf0: A[16K] B[16K]; buf1: A[16K] B[16K]

    const int tid = threadIdx.x;
    const int lane = tid & 31;
    const int wid = tid >> 5;
    const int wm = wid >> 2;          // 0..1
    const int wn = wid & 3;           // 0..3
    const size_t m0 = (size_t)blockIdx.y * 128;
    const size_t n0 = (size_t)blockIdx.x * 128;

    // global load mapping: thread -> (row = tid>>1, 32-bf16 half = tid&1)
    const int arow = tid >> 1;
    const int ahalf = tid & 1;
    const __nv_bfloat16* gA = A2 + (m0 + arow) * K2 + ahalf * 32;
    const __nv_bfloat16* gB = W2 + (n0 + arow) * K2 + ahalf * 32;
    const uint32_t sts_off = (uint32_t)arow * 128u + (uint32_t)ahalf * 64u;

    float acc[4][4][4];
#pragma unroll
    for (int i = 0; i < 4; i++)
#pragma unroll
        for (int j = 0; j < 4; j++)
#pragma unroll
            for (int r = 0; r < 4; r++) acc[i][j][r] = 0.f;

    // preload buffer 0
    {
        char* smA = dbase;
        char* smB = dbase + 16384;
#pragma unroll
        for (int j = 0; j < 4; j++) {
            uint32_t sw = SW128(sts_off + j * 16u);
            *(float4*)(smA + sw) = *(const float4*)(gA + j * 8);
            *(float4*)(smB + sw) = *(const float4*)(gB + j * 8);
        }
    }
    __syncthreads();

    for (int s = 0; s < GSTEPS; s++) {
        // prefetch next step into registers
        uint4 ra[4], rb[4];
        if (s + 1 < GSTEPS) {
            const int k0 = (s + 1) * 64;
#pragma unroll
            for (int j = 0; j < 4; j++) {
                ra[j] = *(const uint4*)(gA + k0 + j * 8);
                rb[j] = *(const uint4*)(gB + k0 + j * 8);
            }
        }

        const uint32_t abase = base + (uint32_t)(s & 1) * 32768u;
        const uint32_t bbase = abase + 16384u;

#pragma unroll
        for (int kat = 0; kat < 4; kat++) {
            uint32_t af[4][4], bf[4][2];
#pragma unroll
            for (int i = 0; i < 4; i++) {
                uint32_t row = (uint32_t)(wm * 64 + i * 16 + (lane & 15));
                uint32_t byte = row * 128u + (uint32_t)kat * 32u + ((lane >> 4) << 4);
                ldsm_x4(af[i], abase + SW128(byte));
            }
#pragma unroll
            for (int j = 0; j < 4; j++) {
                uint32_t row = (uint32_t)(wn * 32 + j * 8 + (lane & 7));
                uint32_t byte = row * 128u + (uint32_t)kat * 32u + (((lane >> 3) & 1) << 4);
                ldsm_x2(bf[j], bbase + SW128(byte));
            }
#pragma unroll
            for (int i = 0; i < 4; i++)
#pragma unroll
                for (int j = 0; j < 4; j++)
                    mma16816(acc[i][j], af[i], bf[j]);
        }

        if (s + 1 < GSTEPS) {
            char* smA = dbase + ((s + 1) & 1) * 32768;
            char* smB = smA + 16384;
#pragma unroll
            for (int j = 0; j < 4; j++) {
                uint32_t sw = SW128(sts_off + j * 16u);
                *(float4*)(smA + sw) = *(float4*)&ra[j];
                *(float4*)(smB + sw) = *(float4*)&rb[j];
            }
        }
        __syncthreads();
    }

    // epilogue
    const int g = lane >> 2;
    const int tig = lane & 3;
#pragma unroll
    for (int i = 0; i < 4; i++) {
        const size_t r0 = m0 + wm * 64 + i * 16 + g;
#pragma unroll
        for (int j = 0; j < 4; j++) {
            const int col = (int)n0 + wn * 32 + j * 8 + tig * 2;
            float2 bb = *(const float2*)(bias + col);
            float2 o0 = make_float2(acc[i][j][0] + bb.x, acc[i][j][1] + bb.y);
            float2 o1 = make_float2(acc[i][j][2] + bb.x, acc[i][j][3] + bb.y);
            *(float2*)(C + r0 * N + col) = o0;
            *(float2*)(C + (r0 + 8) * N + col) = o1;
        }
    }
}

// ---------------------------------------------------------------------------
// Fused causal flash attention (fp32 FFMA), writes split-bf16 ctx directly.
// ---------------------------------------------------------------------------
__global__ __launch_bounds__(128) void attn_kernel(
    const float* __restrict__ qkv, __nv_bfloat16* __restrict__ a2ctx)
{
    extern __shared__ float sm[];
    float* Qs = sm;
    float* Ks = sm + TQ * QPAD;
    float* Vs = Ks + TK * 64;

    const int tid = threadIdx.x;
    const int qt = blockIdx.x;
    const int bh = blockIdx.y;
    const int b = bh >> 4;
    const int hd = bh & 15;
    const int q0 = qt * TQ;
    const int q = q0 + tid;
    const float scale = 0.125f;

    const size_t rs = 3 * HID;
    const float* Qg = qkv + ((size_t)b * SEQ + q0) * rs + hd * HDIM;
    const float* Kg = qkv + ((size_t)b * SEQ) * rs + HID + hd * HDIM;
    const float* Vg = qkv + ((size_t)b * SEQ) * rs + 2 * HID + hd * HDIM;

#pragma unroll
    for (int i = 0; i < 16; i++) {
        int idx = i * 128 + tid;
        int r = idx >> 4;
        int c = (idx & 15) * 4;
        float4 v = *(const float4*)(Qg + (size_t)r * rs + c);
        float* dst = &Qs[r * QPAD + c];
        dst[0] = v.x * scale; dst[1] = v.y * scale;
        dst[2] = v.z * scale; dst[3] = v.w * scale;
    }

    float O[64];
#pragma unroll
    for (int d = 0; d < 64; d++) O[d] = 0.f;
    float m = -CUDART_INF_F;
    float l = 0.f;

    const int kend = q0 + TQ;
    for (int k0 = 0; k0 < kend; k0 += TK) {
        __syncthreads();
#pragma unroll
        for (int i = 0; i < 8; i++) {
            int idx = i * 128 + tid;
            int r = idx >> 4;
            int c = (idx & 15) * 4;
            *(float4*)&Ks[r * 64 + c] = *(const float4*)(Kg + (size_t)(k0 + r) * rs + c);
            *(float4*)&Vs[r * 64 + c] = *(const float4*)(Vg + (size_t)(k0 + r) * rs + c);
        }
        __syncthreads();

        if (q >= k0) {
            float S[64];
#pragma unroll
            for (int j = 0; j < 64; j++) S[j] = 0.f;
#pragma unroll 1
            for (int d4 = 0; d4 < 16; d4++) {
                float4 q4 = *(const float4*)&Qs[tid * QPAD + d4 * 4];
#pragma unroll
                for (int j = 0; j < 64; j++) {
                    float4 k4 = *(const float4*)&Ks[j * 64 + d4 * 4];
                    S[j] = fmaf(q4.x, k4.x, fmaf(q4.y, k4.y,
                           fmaf(q4.z, k4.z, fmaf(q4.w, k4.w, S[j]))));
                }
            }
            const int jlim = q - k0;
            float mnew = m;
#pragma unroll
            for (int j = 0; j < 64; j++) {
                if (j > jlim) S[j] = -CUDART_INF_F;
                mnew = fmaxf(mnew, S[j]);
            }
            float corr = __expf(m - mnew);
            m = mnew;
            float lsum = 0.f;
#pragma unroll
            for (int j = 0; j < 64; j++) {
                float p = __expf(S[j] - mnew);
                S[j] = p;
                lsum += p;
            }
            l = l * corr + lsum;
#pragma unroll
            for (int d = 0; d < 64; d++) O[d] *= corr;
#pragma unroll
            for (int j = 0; j < 64; j++) {
                float p = S[j];
#pragma unroll
                for (int d4 = 0; d4 < 16; d4++) {
                    float4 v4 = *(const float4*)&Vs[j * 64 + d4 * 4];
                    O[d4 * 4 + 0] = fmaf(p, v4.x, O[d4 * 4 + 0]);
                    O[d4 * 4 + 1] = fmaf(p, v4.y, O[d4 * 4 + 1]);
                    O[d4 * 4 + 2] = fmaf(p, v4.z, O[d4 * 4 + 2]);
                    O[d4 * 4 + 3] = fmaf(p, v4.w, O[d4 * 4 + 3]);
                }
            }
        }
    }

    // epilogue: split ctx into [hi | lo | hi] bf16 row of width 3*HID
    const float inv = 1.f / l;
    __nv_bfloat16* rowp = a2ctx + ((size_t)b * SEQ + q) * K2 + hd * HDIM;
#pragma unroll
    for (int d4 = 0; d4 < 16; d4++) {
        float o0 = O[d4 * 4 + 0] * inv, o1 = O[d4 * 4 + 1] * inv;
        float o2 = O[d4 * 4 + 2] * inv, o3 = O[d4 * 4 + 3] * inv;
        __nv_bfloat16 h0 = __float2bfloat16(o0), h1 = __float2bfloat16(o1);
        __nv_bfloat16 h2 = __float2bfloat16(o2), h3 = __float2bfloat16(o3);
        uint2 hi = make_uint2(pack2bf(__bfloat162float(h0), __bfloat162float(h1)),
                              pack2bf(__bfloat162float(h2), __bfloat162float(h3)));
        uint2 lo = make_uint2(pack2bf(o0 - __bfloat162float(h0), o1 - __bfloat162float(h1)),
                              pack2bf(o2 - __bfloat162float(h2), o3 - __bfloat162float(h3)));
        *(uint2*)(rowp + d4 * 4) = hi;
        *(uint2*)(rowp + HID + d4 * 4) = lo;
        *(uint2*)(rowp + 2 * HID + d4 * 4) = hi;
    }
}

// ---------------------------------------------------------------------------
extern "C" void kernel_launch(void* const* d_in, const int* in_sizes, int n_in,
                              void* d_out, int out_size)
{
    (void)in_sizes; (void)n_in; (void)out_size;
    const float* x     = (const float*)d_in[0];
    const float* W_qkv = (const float*)d_in[2];
    const float* b_qkv = (const float*)d_in[3];
    const float* W_out = (const float*)d_in[4];
    const float* b_out = (const float*)d_in[5];
    float* out = (float*)d_out;

    float* qkv = nullptr;
    __nv_bfloat16 *a2x = nullptr, *w2qkv = nullptr, *a2ctx = nullptr, *w2out = nullptr;
    cudaGetSymbolAddress((void**)&qkv, g_qkv);
    cudaGetSymbolAddress((void**)&a2x, g_a2x);
    cudaGetSymbolAddress((void**)&w2qkv, g_w2qkv);
    cudaGetSymbolAddress((void**)&a2ctx, g_a2ctx);
    cudaGetSymbolAddress((void**)&w2out, g_w2out);

    const int gemm_smem = 64 * 1024 + 1024;
    cudaFuncSetAttribute(gemm_mma_kernel, cudaFuncAttributeMaxDynamicSharedMemorySize, gemm_smem);
    const size_t attn_smem = (size_t)(TQ * QPAD + TK * 64 * 2) * sizeof(float);
    cudaFuncSetAttribute(attn_kernel, cudaFuncAttributeMaxDynamicSharedMemorySize, (int)attn_smem);

    // 0) split-precision conversions
    split_kernel<<<(BT * HID / 4 + 255) / 256, 256>>>(x, a2x, HID, (size_t)BT * HID / 4, 1, 2);
    split_kernel<<<(3 * HID * HID / 4 + 255) / 256, 256>>>(W_qkv, w2qkv, HID, (size_t)3 * HID * HID / 4, 2, 1);
    split_kernel<<<(HID * HID / 4 + 255) / 256, 256>>>(W_out, w2out, HID, (size_t)HID * HID / 4, 2, 1);

    // 1) QKV projection (HMMA): [8192,3072] x [3072,3072]^T
    gemm_mma_kernel<<<dim3(3 * HID / 128, BT / 128), 256, gemm_smem>>>(a2x, w2qkv, b_qkv, qkv, 3 * HID);

    // 2) fused causal attention -> split-bf16 ctx
    attn_kernel<<<dim3(SEQ / TQ, 4 * NHEADS), 128, attn_smem>>>(qkv, a2ctx);

    // 3) output projection (HMMA): [8192,3072] x [1024,3072]^T
    gemm_mma_kernel<<<dim3(HID / 128, BT / 128), 256, gemm_smem>>>(a2ctx, w2out, b_out, out, HID);
}

// round 5
// speedup vs baseline: 1.2723x; 1.0080x over previous
#include <cuda_runtime.h>
#include <cuda_bf16.h>
#include <math_constants.h>
#include <cstdint>

#define HID 1024
#define NHEADS 16
#define HDIM 64
#define SEQ 2048
#define BT 8192
#define TQ 128
#define TK 64
#define QPAD 68
#define K2 3072            // split-GEMM K' = 3*HID
#define GSTEPS (K2 / 64)   // 48 k-steps of 64 bf16

// ---------------------------------------------------------------------------
// Scratch (__device__ globals: runtime allocation is forbidden)
// ---------------------------------------------------------------------------
__device__ float         g_qkv[(size_t)BT * 3 * HID];     // fp32 [BT, 3H]
__device__ __nv_bfloat16 g_a2x[(size_t)BT * K2];          // [Ah|Al|Ah] of x
__device__ __nv_bfloat16 g_w2qkv[(size_t)3 * HID * K2];   // [Wh|Wh|Wl] of W_qkv
__device__ __nv_bfloat16 g_a2ctx[(size_t)BT * K2];        // [Ah|Al|Ah] of ctx
__device__ __nv_bfloat16 g_w2out[(size_t)HID * K2];       // [Wh|Wh|Wl] of W_out

// ---------------------------------------------------------------------------
// helpers
// ---------------------------------------------------------------------------
__device__ __forceinline__ uint32_t smem_to_u32(const void* p) {
    uint32_t a;
    asm("{ .reg .u64 t; cvta.to.shared.u64 t, %1; cvt.u32.u64 %0, t; }"
        : "=r"(a) : "l"(p));
    return a;
}
#define SW128(b) ((b) ^ (((b) >> 3) & 0x70u))

__device__ __forceinline__ void ldsm_x4(uint32_t* r, uint32_t addr) {
    asm volatile("ldmatrix.sync.aligned.m8n8.x4.shared.b16 {%0,%1,%2,%3}, [%4];"
        : "=r"(r[0]), "=r"(r[1]), "=r"(r[2]), "=r"(r[3]) : "r"(addr));
}
__device__ __forceinline__ void ldsm_x2(uint32_t* r, uint32_t addr) {
    asm volatile("ldmatrix.sync.aligned.m8n8.x2.shared.b16 {%0,%1}, [%2];"
        : "=r"(r[0]), "=r"(r[1]) : "r"(addr));
}
__device__ __forceinline__ void mma16816(float* d, const uint32_t* a, const uint32_t* b) {
    asm volatile("mma.sync.aligned.m16n8k16.row.col.f32.bf16.bf16.f32 "
        "{%0,%1,%2,%3}, {%4,%5,%6,%7}, {%8,%9}, {%0,%1,%2,%3};"
        : "+f"(d[0]), "+f"(d[1]), "+f"(d[2]), "+f"(d[3])
        : "r"(a[0]), "r"(a[1]), "r"(a[2]), "r"(a[3]), "r"(b[0]), "r"(b[1]));
}

__device__ __forceinline__ uint32_t pack2bf(float a, float b) {
    __nv_bfloat162 t = __floats2bfloat162_rn(a, b);
    return *reinterpret_cast<uint32_t*>(&t);
}

// ---------------------------------------------------------------------------
// Split convert: src fp32 [rows, K] -> dst bf16 [rows, 3K]
//   block 0 = hi; block lo_blk = lo; block hi2_blk = hi (duplicate)
//   A-side: lo_blk=1, hi2_blk=2.  W-side: lo_blk=2, hi2_blk=1.
// ---------------------------------------------------------------------------
__global__ __launch_bounds__(256) void split_kernel(
    const float* __restrict__ src, __nv_bfloat16* __restrict__ dst,
    int K, size_t total4, int lo_blk, int hi2_blk)
{
    size_t idx = (size_t)blockIdx.x * blockDim.x + threadIdx.x;
    if (idx >= total4) return;
    int kq = K >> 2;
    size_t r = idx / kq;
    int c = (int)(idx % kq) << 2;
    float4 v = *(const float4*)(src + r * K + c);

    __nv_bfloat16 h0 = __float2bfloat16(v.x), h1 = __float2bfloat16(v.y);
    __nv_bfloat16 h2 = __float2bfloat16(v.z), h3 = __float2bfloat16(v.w);
    float l0 = v.x - __bfloat162float(h0), l1 = v.y - __bfloat162float(h1);
    float l2 = v.z - __bfloat162float(h2), l3 = v.w - __bfloat162float(h3);

    uint2 hi = make_uint2(pack2bf(__bfloat162float(h0), __bfloat162float(h1)),
                          pack2bf(__bfloat162float(h2), __bfloat162float(h3)));
    uint2 lo = make_uint2(pack2bf(l0, l1), pack2bf(l2, l3));

    __nv_bfloat16* drow = dst + r * (size_t)(3 * K);
    *(uint2*)(drow + c) = hi;
    *(uint2*)(drow + (size_t)lo_blk * K + c) = lo;
    *(uint2*)(drow + (size_t)hi2_blk * K + c) = hi;
}

// ---------------------------------------------------------------------------
// mma.sync bf16 GEMM: C[M,N] = A2[M,K2] @ W2[N,K2]^T + bias
// CTA tile 128x128, BK=64, 256 threads (8 warps, 2x4), warp tile 64x32.
// SW128-swizzled smem (128B rows), double buffered.
// ---------------------------------------------------------------------------
__global__ __launch_bounds__(256) void gemm_mma_kernel(
    const __nv_bfloat16* __restrict__ A2, const __nv_bfloat16* __restrict__ W2,
    const float* __restrict__ bias, float* __restrict__ C, int N)
{
    extern __shared__ char dsm[];
    const uint32_t dyn = smem_to_u32(dsm);
    const uint32_t base = (dyn + 1023u) & ~1023u;
    char* dbase = dsm + (base - dyn);
    // layout: buf0: A[16K] B[16K]; buf1: A[16K] B[16K]

    const int tid = threadIdx.x;
    const int lane = tid & 31;
    const int wid = tid >> 5;
    const int wm = wid >> 2;          // 0..1
    const int wn = wid & 3;           // 0..3
    const size_t m0 = (size_t)blockIdx.y * 128;
    const size_t n0 = (size_t)blockIdx.x * 128;

    // global load mapping: thread -> (row = tid>>1, 32-bf16 half = tid&1)
    const int arow = tid >> 1;
    const int ahalf = tid & 1;
    const __nv_bfloat16* gA = A2 + (m0 + arow) * K2 + ahalf * 32;
    const __nv_bfloat16* gB = W2 + (n0 + arow) * K2 + ahalf * 32;
    const uint32_t sts_off = (uint32_t)arow * 128u + (uint32_t)ahalf * 64u;

    float acc[4][4][4];
#pragma unroll
    for (int i = 0; i < 4; i++)
#pragma unroll
        for (int j = 0; j < 4; j++)
#pragma unroll
            for (int r = 0; r < 4; r++) acc[i][j][r] = 0.f;

    // preload buffer 0
    {
        char* smA = dbase;
        char* smB = dbase + 16384;
#pragma unroll
        for (int j = 0; j < 4; j++) {
            uint32_t sw = SW128(sts_off + j * 16u);
            *(float4*)(smA + sw) = *(const float4*)(gA + j * 8);
            *(float4*)(smB + sw) = *(const float4*)(gB + j * 8);
        }
    }
    __syncthreads();

    for (int s = 0; s < GSTEPS; s++) {
        // prefetch next step into registers
        uint4 ra[4], rb[4];
        if (s + 1 < GSTEPS) {
            const int k0 = (s + 1) * 64;
#pragma unroll
            for (int j = 0; j < 4; j++) {
                ra[j] = *(const uint4*)(gA + k0 + j * 8);
                rb[j] = *(const uint4*)(gB + k0 + j * 8);
            }
        }

        const uint32_t abase = base + (uint32_t)(s & 1) * 32768u;
        const uint32_t bbase = abase + 16384u;

#pragma unroll
        for (int kat = 0; kat < 4; kat++) {
            uint32_t af[4][4], bf[4][2];
#pragma unroll
            for (int i = 0; i < 4; i++) {
                uint32_t row = (uint32_t)(wm * 64 + i * 16 + (lane & 15));
                uint32_t byte = row * 128u + (uint32_t)kat * 32u + ((lane >> 4) << 4);
                ldsm_x4(af[i], abase + SW128(byte));
            }
#pragma unroll
            for (int j = 0; j < 4; j++) {
                uint32_t row = (uint32_t)(wn * 32 + j * 8 + (lane & 7));
                uint32_t byte = row * 128u + (uint32_t)kat * 32u + (((lane >> 3) & 1) << 4);
                ldsm_x2(bf[j], bbase + SW128(byte));
            }
#pragma unroll
            for (int i = 0; i < 4; i++)
#pragma unroll
                for (int j = 0; j < 4; j++)
                    mma16816(acc[i][j], af[i], bf[j]);
        }

        if (s + 1 < GSTEPS) {
            char* smA = dbase + ((s + 1) & 1) * 32768;
            char* smB = smA + 16384;
#pragma unroll
            for (int j = 0; j < 4; j++) {
                uint32_t sw = SW128(sts_off + j * 16u);
                *(float4*)(smA + sw) = *(float4*)&ra[j];
                *(float4*)(smB + sw) = *(float4*)&rb[j];
            }
        }
        __syncthreads();
    }

    // epilogue
    const int g = lane >> 2;
    const int tig = lane & 3;
#pragma unroll
    for (int i = 0; i < 4; i++) {
        const size_t r0 = m0 + wm * 64 + i * 16 + g;
#pragma unroll
        for (int j = 0; j < 4; j++) {
            const int col = (int)n0 + wn * 32 + j * 8 + tig * 2;
            float2 bb = *(const float2*)(bias + col);
            float2 o0 = make_float2(acc[i][j][0] + bb.x, acc[i][j][1] + bb.y);
            float2 o1 = make_float2(acc[i][j][2] + bb.x, acc[i][j][3] + bb.y);
            *(float2*)(C + r0 * N + col) = o0;
            *(float2*)(C + (r0 + 8) * N + col) = o1;
        }
    }
}

// ---------------------------------------------------------------------------
// Fused causal flash attention (fp32 FFMA), writes split-bf16 ctx directly.
// ---------------------------------------------------------------------------
__global__ __launch_bounds__(128) void attn_kernel(
    const float* __restrict__ qkv, __nv_bfloat16* __restrict__ a2ctx)
{
    extern __shared__ float sm[];
    float* Qs = sm;
    float* Ks = sm + TQ * QPAD;
    float* Vs = Ks + TK * 64;

    const int tid = threadIdx.x;
    const int qt = blockIdx.x;
    const int bh = blockIdx.y;
    const int b = bh >> 4;
    const int hd = bh & 15;
    const int q0 = qt * TQ;
    const int q = q0 + tid;
    const float scale = 0.125f;

    const size_t rs = 3 * HID;
    const float* Qg = qkv + ((size_t)b * SEQ + q0) * rs + hd * HDIM;
    const float* Kg = qkv + ((size_t)b * SEQ) * rs + HID + hd * HDIM;
    const float* Vg = qkv + ((size_t)b * SEQ) * rs + 2 * HID + hd * HDIM;

#pragma unroll
    for (int i = 0; i < 16; i++) {
        int idx = i * 128 + tid;
        int r = idx >> 4;
        int c = (idx & 15) * 4;
        float4 v = *(const float4*)(Qg + (size_t)r * rs + c);
        float* dst = &Qs[r * QPAD + c];
        dst[0] = v.x * scale; dst[1] = v.y * scale;
        dst[2] = v.z * scale; dst[3] = v.w * scale;
    }

    float O[64];
#pragma unroll
    for (int d = 0; d < 64; d++) O[d] = 0.f;
    float m = -CUDART_INF_F;
    float l = 0.f;

    const int kend = q0 + TQ;
    for (int k0 = 0; k0 < kend; k0 += TK) {
        __syncthreads();
#pragma unroll
        for (int i = 0; i < 8; i++) {
            int idx = i * 128 + tid;
            int r = idx >> 4;
            int c = (idx & 15) * 4;
            *(float4*)&Ks[r * 64 + c] = *(const float4*)(Kg + (size_t)(k0 + r) * rs + c);
            *(float4*)&Vs[r * 64 + c] = *(const float4*)(Vg + (size_t)(k0 + r) * rs + c);
        }
        __syncthreads();

        if (q >= k0) {
            float S[64];
#pragma unroll
            for (int j = 0; j < 64; j++) S[j] = 0.f;
#pragma unroll 1
            for (int d4 = 0; d4 < 16; d4++) {
                float4 q4 = *(const float4*)&Qs[tid * QPAD + d4 * 4];
#pragma unroll
                for (int j = 0; j < 64; j++) {
                    float4 k4 = *(const float4*)&Ks[j * 64 + d4 * 4];
                    S[j] = fmaf(q4.x, k4.x, fmaf(q4.y, k4.y,
                           fmaf(q4.z, k4.z, fmaf(q4.w, k4.w, S[j]))));
                }
            }
            const int jlim = q - k0;
            float mnew = m;
#pragma unroll
            for (int j = 0; j < 64; j++) {
                if (j > jlim) S[j] = -CUDART_INF_F;
                mnew = fmaxf(mnew, S[j]);
            }
            float corr = __expf(m - mnew);
            m = mnew;
            float lsum = 0.f;
#pragma unroll
            for (int j = 0; j < 64; j++) {
                float p = __expf(S[j] - mnew);
                S[j] = p;
                lsum += p;
            }
            l = l * corr + lsum;
#pragma unroll
            for (int d = 0; d < 64; d++) O[d] *= corr;
#pragma unroll
            for (int j = 0; j < 64; j++) {
                float p = S[j];
#pragma unroll
                for (int d4 = 0; d4 < 16; d4++) {
                    float4 v4 = *(const float4*)&Vs[j * 64 + d4 * 4];
                    O[d4 * 4 + 0] = fmaf(p, v4.x, O[d4 * 4 + 0]);
                    O[d4 * 4 + 1] = fmaf(p, v4.y, O[d4 * 4 + 1]);
                    O[d4 * 4 + 2] = fmaf(p, v4.z, O[d4 * 4 + 2]);
                    O[d4 * 4 + 3] = fmaf(p, v4.w, O[d4 * 4 + 3]);
                }
            }
        }
    }

    // epilogue: split ctx into [hi | lo | hi] bf16 row of width 3*HID
    const float inv = 1.f / l;
    __nv_bfloat16* rowp = a2ctx + ((size_t)b * SEQ + q) * K2 + hd * HDIM;
#pragma unroll
    for (int d4 = 0; d4 < 16; d4++) {
        float o0 = O[d4 * 4 + 0] * inv, o1 = O[d4 * 4 + 1] * inv;
        float o2 = O[d4 * 4 + 2] * inv, o3 = O[d4 * 4 + 3] * inv;
        __nv_bfloat16 h0 = __float2bfloat16(o0), h1 = __float2bfloat16(o1);
        __nv_bfloat16 h2 = __float2bfloat16(o2), h3 = __float2bfloat16(o3);
        uint2 hi = make_uint2(pack2bf(__bfloat162float(h0), __bfloat162float(h1)),
                              pack2bf(__bfloat162float(h2), __bfloat162float(h3)));
        uint2 lo = make_uint2(pack2bf(o0 - __bfloat162float(h0), o1 - __bfloat162float(h1)),
                              pack2bf(o2 - __bfloat162float(h2), o3 - __bfloat162float(h3)));
        *(uint2*)(rowp + d4 * 4) = hi;
        *(uint2*)(rowp + HID + d4 * 4) = lo;
        *(uint2*)(rowp + 2 * HID + d4 * 4) = hi;
    }
}

// ---------------------------------------------------------------------------
extern "C" void kernel_launch(void* const* d_in, const int* in_sizes, int n_in,
                              void* d_out, int out_size)
{
    (void)in_sizes; (void)n_in; (void)out_size;
    const float* x     = (const float*)d_in[0];
    const float* W_qkv = (const float*)d_in[2];
    const float* b_qkv = (const float*)d_in[3];
    const float* W_out = (const float*)d_in[4];
    const float* b_out = (const float*)d_in[5];
    float* out = (float*)d_out;

    float* qkv = nullptr;
    __nv_bfloat16 *a2x = nullptr, *w2qkv = nullptr, *a2ctx = nullptr, *w2out = nullptr;
    cudaGetSymbolAddress((void**)&qkv, g_qkv);
    cudaGetSymbolAddress((void**)&a2x, g_a2x);
    cudaGetSymbolAddress((void**)&w2qkv, g_w2qkv);
    cudaGetSymbolAddress((void**)&a2ctx, g_a2ctx);
    cudaGetSymbolAddress((void**)&w2out, g_w2out);

    const int gemm_smem = 64 * 1024 + 1024;
    cudaFuncSetAttribute(gemm_mma_kernel, cudaFuncAttributeMaxDynamicSharedMemorySize, gemm_smem);
    const size_t attn_smem = (size_t)(TQ * QPAD + TK * 64 * 2) * sizeof(float);
    cudaFuncSetAttribute(attn_kernel, cudaFuncAttributeMaxDynamicSharedMemorySize, (int)attn_smem);

    // 0) split-precision conversions
    split_kernel<<<(BT * HID / 4 + 255) / 256, 256>>>(x, a2x, HID, (size_t)BT * HID / 4, 1, 2);
    split_kernel<<<(3 * HID * HID / 4 + 255) / 256, 256>>>(W_qkv, w2qkv, HID, (size_t)3 * HID * HID / 4, 2, 1);
    split_kernel<<<(HID * HID / 4 + 255) / 256, 256>>>(W_out, w2out, HID, (size_t)HID * HID / 4, 2, 1);

    // 1) QKV projection (HMMA): [8192,3072] x [3072,3072]^T
    gemm_mma_kernel<<<dim3(3 * HID / 128, BT / 128), 256, gemm_smem>>>(a2x, w2qkv, b_qkv, qkv, 3 * HID);

    // 2) fused causal attention -> split-bf16 ctx
    attn_kernel<<<dim3(SEQ / TQ, 4 * NHEADS), 128, attn_smem>>>(qkv, a2ctx);

    // 3) output projection (HMMA): [8192,3072] x [1024,3072]^T
    gemm_mma_kernel<<<dim3(HID / 128, BT / 128), 256, gemm_smem>>>(a2ctx, w2out, b_out, out, HID);
}